// round 10
// baseline (speedup 1.0000x reference)
#include <cuda_runtime.h>
#include <cstdint>
#include <cstddef>

// Problem constants
#define NB   512
#define NT   2048
#define NXD  32
#define NUD  8
#define NYD  16
#define NH   128
#define NTHD 4
#define ZF_DIM 44   // NXD + NUD + NTHD
#define ZH_DIM 36   // NXD + NTHD

#define THREADS 256   // 2 batch rows per block, 8 warps

// Exact XLA EmitFastTanh — bitwise-matched to the reference (verified rel_err=0).
__device__ __forceinline__ float xla_tanh(float x) {
    const float kClamp = 7.90531110763549805f;
    float ax = fabsf(x);
    float xc = fminf(fmaxf(x, -kClamp), kClamp);
    float x2 = __fmul_rn(xc, xc);
    float p;
    p = __fmaf_rn(x2, -2.76076847742355e-16f, 2.00018790482477e-13f);
    p = __fmaf_rn(x2, p, -8.60467152213735e-11f);
    p = __fmaf_rn(x2, p,  5.12229709037114e-08f);
    p = __fmaf_rn(x2, p,  1.48572235717979e-05f);
    p = __fmaf_rn(x2, p,  6.37261928875436e-04f);
    p = __fmaf_rn(x2, p,  4.89352455891786e-03f);
    p = __fmul_rn(xc, p);
    float q;
    q = __fmaf_rn(x2, 1.19825839466702e-06f, 1.18534705686654e-04f);
    q = __fmaf_rn(x2, q, 2.26843463243900e-03f);
    q = __fmaf_rn(x2, q, 4.89352518554385e-03f);
    float r = __fdiv_rn(p, q);
    return (ax < 0.0004f) ? x : r;
}

// Named barriers: 1 = {w0..w3, w6, w7} (192 thr, hf ready); 2 = {w6,w7} (64 thr).
#define BAR1() asm volatile("bar.sync 1, 192;" ::: "memory")
#define BAR2() asm volatile("bar.sync 2, 64;"  ::: "memory")

__global__ void __launch_bounds__(THREADS, 2)
ssm_kernel(const float* __restrict__ x0g, const float* __restrict__ ug,
           const float* __restrict__ thfg, const float* __restrict__ thhg,
           const float* __restrict__ Wf1g, const float* __restrict__ bf1g,
           const float* __restrict__ Wf2g, const float* __restrict__ bf2g,
           const float* __restrict__ Wh1g, const float* __restrict__ bh1g,
           const float* __restrict__ Wh2g, const float* __restrict__ bh2g,
           const float* __restrict__ xming, const float* __restrict__ xmaxg,
           const float* __restrict__ yming, const float* __restrict__ ymaxg,
           float* __restrict__ outx, float* __restrict__ outy)
{
    __shared__ __align__(16) float WH2T[NYD * 132];   // WH2T[i*132+k] = Wh2[k][i]
    __shared__ __align__(16) float hfA[NH], hfB[NH];
    __shared__ __align__(16) float hhA0[NH], hhA1[NH], hhB0[NH], hhB1[NH];
    __shared__ __align__(16) float zfA0[48], zfA1[48], zfB0[48], zfB1[48];
    __shared__ __align__(16) float zhA0[48], zhA1[48], zhB0[48], zhB1[48];
    __shared__ __align__(16) float pA[32], pB[32];    // f2 segment partials

    const int tt   = threadIdx.x;
    const int w    = tt >> 5;
    const int lane = tt & 31;
    const int bA   = blockIdx.x * 2;
    const int bB   = bA + 1;

    const float* ubA = ug + (size_t)bA * NT * NUD;
    const float* ubB = ug + (size_t)bB * NT * NUD;
    float* oxA = outx + (size_t)bA * NT * NXD;
    float* oxB = outx + (size_t)bB * NT * NXD;
    float* oyA = outy + (size_t)bA * NT * NYD;
    float* oyB = outy + (size_t)bB * NT * NYD;

    // ---- role-specific register weights ----
    float wF[ZF_DIM]; float bF = 0.f;                    // w0-w3: f1 col tt
    float wh[2 * ZH_DIM]; float bH0 = 0.f, bH1 = 0.f;    // w4,w5: h1 cols j, j+64
    float wx2[64];                                       // w6/w7: f2 seg weights
    float bf2v = 0.f, xlo = 0.f, xhi = 0.f;              // w7
    float bh2v = 0.f, ylo = 0.f, yhi = 0.f;              // w2 (h2)

    if (tt < 128) {
#pragma unroll
        for (int k = 0; k < ZF_DIM; k++) wF[k] = Wf1g[k * NH + tt];
        bF = bf1g[tt];
        if (w == 2) {
            bh2v = bh2g[(tt - 64) & 15];
            ylo = yming[0]; yhi = ymaxg[0];
        }
    } else if (tt < 192) {
        const int j = tt - 128;
#pragma unroll
        for (int k = 0; k < ZH_DIM; k++) {
            wh[k]          = Wh1g[k * NH + j];
            wh[ZH_DIM + k] = Wh1g[k * NH + 64 + j];
        }
        bH0 = bh1g[j];
        bH1 = bh1g[64 + j];
    } else if (tt < 224) {
#pragma unroll
        for (int k = 0; k < 64; k++) wx2[k] = Wf2g[k * NXD + lane];
    } else {
#pragma unroll
        for (int k = 0; k < 64; k++) wx2[k] = Wf2g[(64 + k) * NXD + lane];
        bf2v = bf2g[lane];
        xlo = xming[0]; xhi = xmaxg[0];
    }

    // ---- smem staging ----
    for (int e = tt; e < NH * NYD; e += THREADS) {
        int k = e >> 4, i = e & 15;
        WH2T[i * 132 + k] = Wh2g[e];
    }
    if (tt < 32) {
        float xvA = x0g[bA * 32 + tt];
        float xvB = x0g[bB * 32 + tt];
        zfA0[tt] = xvA;  zhA1[tt] = xvA;  oxA[tt] = xvA;
        zfB0[tt] = xvB;  zhB1[tt] = xvB;  oxB[tt] = xvB;
    } else if (tt < 40) {
        zfA0[tt] = ubA[tt - 32];
        zfB0[tt] = ubB[tt - 32];
    } else if (tt < 44) {
        float tA = thfg[bA * 4 + (tt - 40)];
        float tB = thfg[bB * 4 + (tt - 40)];
        zfA0[tt] = tA; zfA1[tt] = tA;
        zfB0[tt] = tB; zfB1[tt] = tB;
    } else if (tt < 48) {
        float tA = thhg[bA * 4 + (tt - 44)];
        float tB = thhg[bB * 4 + (tt - 44)];
        zhA0[32 + (tt - 44)] = tA; zhA1[32 + (tt - 44)] = tA;
        zhB0[32 + (tt - 44)] = tB; zhB1[32 + (tt - 44)] = tB;
    }
    __syncthreads();

    // ---- one step: f(t) + h1(t) + h2(t-1), all buffer parity static ----
    auto step = [&](int t,
                    const float* zfAc, const float* zfBc, float* zfAn, float* zfBn,
                    float* zhAw, float* zhBw, const float* zhAr, const float* zhBr,
                    float* hhAw, float* hhBw, const float* hhAr, const float* hhBr)
    {
        if (tt < 128) {
            // ---- f1: unit tt for rows A and B (2 ILP chains, reg weights) ----
            float a0 = 0.f, a1 = 0.f;
#pragma unroll
            for (int q = 0; q < ZF_DIM / 4; q++) {
                float4 zA = *(const float4*)(zfAc + 4 * q);
                float4 zB = *(const float4*)(zfBc + 4 * q);
                a0 = __fmaf_rn(zA.x, wF[4 * q + 0], a0);
                a1 = __fmaf_rn(zB.x, wF[4 * q + 0], a1);
                a0 = __fmaf_rn(zA.y, wF[4 * q + 1], a0);
                a1 = __fmaf_rn(zB.y, wF[4 * q + 1], a1);
                a0 = __fmaf_rn(zA.z, wF[4 * q + 2], a0);
                a1 = __fmaf_rn(zB.z, wF[4 * q + 2], a1);
                a0 = __fmaf_rn(zA.w, wF[4 * q + 3], a0);
                a1 = __fmaf_rn(zB.w, wF[4 * q + 3], a1);
            }
            hfA[tt] = xla_tanh(__fadd_rn(a0, bF));
            hfB[tt] = xla_tanh(__fadd_rn(a1, bF));
            BAR1();
            if (w == 2 && t > 0) {
                // ---- h2(t-1): 32 chains (lanes 0-15 row A, 16-31 row B) ----
                const int l = tt - 64;
                const int out = l & 15;
                const float* hhp = (l < 16) ? hhAr : hhBr;
                const float* wr  = WH2T + out * 132;
                float acc = 0.f;
#pragma unroll
                for (int q = 0; q < NH / 4; q++) {
                    float4 h4 = *(const float4*)(hhp + 4 * q);
                    float4 w4 = *(const float4*)(wr + 4 * q);
                    acc = __fmaf_rn(h4.x, w4.x, acc);
                    acc = __fmaf_rn(h4.y, w4.y, acc);
                    acc = __fmaf_rn(h4.z, w4.z, acc);
                    acc = __fmaf_rn(h4.w, w4.w, acc);
                }
                float y = __fadd_rn(acc, bh2v);
                if (t > 1) y = fminf(fmaxf(y, ylo), yhi);   // y[0] unclamped
                ((l < 16) ? oyA : oyB)[(size_t)(t - 1) * NYD + out] = y;
            }
        } else if (tt < 192) {
            // ---- h1(t): cols j and j+64, rows A and B (4 ILP chains) ----
            const int j = tt - 128;
            float c0 = 0.f, c1 = 0.f, c2 = 0.f, c3 = 0.f;
#pragma unroll
            for (int q = 0; q < ZH_DIM / 4; q++) {
                float4 zA = *(const float4*)(zhAr + 4 * q);
                float4 zB = *(const float4*)(zhBr + 4 * q);
                c0 = __fmaf_rn(zA.x, wh[4 * q + 0], c0);
                c1 = __fmaf_rn(zA.x, wh[ZH_DIM + 4 * q + 0], c1);
                c2 = __fmaf_rn(zB.x, wh[4 * q + 0], c2);
                c3 = __fmaf_rn(zB.x, wh[ZH_DIM + 4 * q + 0], c3);
                c0 = __fmaf_rn(zA.y, wh[4 * q + 1], c0);
                c1 = __fmaf_rn(zA.y, wh[ZH_DIM + 4 * q + 1], c1);
                c2 = __fmaf_rn(zB.y, wh[4 * q + 1], c2);
                c3 = __fmaf_rn(zB.y, wh[ZH_DIM + 4 * q + 1], c3);
                c0 = __fmaf_rn(zA.z, wh[4 * q + 2], c0);
                c1 = __fmaf_rn(zA.z, wh[ZH_DIM + 4 * q + 2], c1);
                c2 = __fmaf_rn(zB.z, wh[4 * q + 2], c2);
                c3 = __fmaf_rn(zB.z, wh[ZH_DIM + 4 * q + 2], c3);
                c0 = __fmaf_rn(zA.w, wh[4 * q + 3], c0);
                c1 = __fmaf_rn(zA.w, wh[ZH_DIM + 4 * q + 3], c1);
                c2 = __fmaf_rn(zB.w, wh[4 * q + 3], c2);
                c3 = __fmaf_rn(zB.w, wh[ZH_DIM + 4 * q + 3], c3);
            }
            hhAw[j]      = xla_tanh(__fadd_rn(c0, bH0));
            hhAw[j + 64] = xla_tanh(__fadd_rn(c1, bH1));
            hhBw[j]      = xla_tanh(__fadd_rn(c2, bH0));
            hhBw[j + 64] = xla_tanh(__fadd_rn(c3, bH1));
        } else if (tt < 224) {
            // ---- w6: f2 segment A (k=0..63), rows A and B, reg weights ----
            BAR1();
            float accA = 0.f, accB = 0.f;
#pragma unroll
            for (int q = 0; q < 16; q++) {
                float4 hA = *(const float4*)(hfA + 4 * q);
                float4 hB = *(const float4*)(hfB + 4 * q);
                accA = __fmaf_rn(hA.x, wx2[4 * q + 0], accA);
                accB = __fmaf_rn(hB.x, wx2[4 * q + 0], accB);
                accA = __fmaf_rn(hA.y, wx2[4 * q + 1], accA);
                accB = __fmaf_rn(hB.y, wx2[4 * q + 1], accB);
                accA = __fmaf_rn(hA.z, wx2[4 * q + 2], accA);
                accB = __fmaf_rn(hB.z, wx2[4 * q + 2], accB);
                accA = __fmaf_rn(hA.w, wx2[4 * q + 3], accA);
                accB = __fmaf_rn(hB.w, wx2[4 * q + 3], accB);
            }
            pA[lane] = accA;
            pB[lane] = accB;
            BAR2();
        } else {
            // ---- w7: u loads, f2 segment B (k=64..127), state update ----
            float uA = 0.f, uB = 0.f;
            if (lane < 8)       uA = ubA[(size_t)(t + 1) * NUD + lane];
            else if (lane < 16) uB = ubB[(size_t)(t + 1) * NUD + (lane - 8)];
            if (lane == 16 && t + 8 < NT)
                asm volatile("prefetch.global.L2 [%0];" :: "l"(ubA + (size_t)(t + 8) * NUD));
            if (lane == 17 && t + 8 < NT)
                asm volatile("prefetch.global.L2 [%0];" :: "l"(ubB + (size_t)(t + 8) * NUD));
            BAR1();
            BAR2();
            float accA = pA[lane], accB = pB[lane];
#pragma unroll
            for (int q = 0; q < 16; q++) {
                float4 hA = *(const float4*)(hfA + 64 + 4 * q);
                float4 hB = *(const float4*)(hfB + 64 + 4 * q);
                accA = __fmaf_rn(hA.x, wx2[4 * q + 0], accA);
                accB = __fmaf_rn(hB.x, wx2[4 * q + 0], accB);
                accA = __fmaf_rn(hA.y, wx2[4 * q + 1], accA);
                accB = __fmaf_rn(hB.y, wx2[4 * q + 1], accB);
                accA = __fmaf_rn(hA.z, wx2[4 * q + 2], accA);
                accB = __fmaf_rn(hB.z, wx2[4 * q + 2], accB);
                accA = __fmaf_rn(hA.w, wx2[4 * q + 3], accA);
                accB = __fmaf_rn(hB.w, wx2[4 * q + 3], accB);
            }
            float dxA = __fadd_rn(accA, bf2v);
            float dxB = __fadd_rn(accB, bf2v);
            float xnA = __fadd_rn(zfAc[lane], dxA);
            float xnB = __fadd_rn(zfBc[lane], dxB);
            zhAw[lane] = xnA;                       // h input for next step
            zhBw[lane] = xnB;
            float xcA = fminf(fmaxf(xnA, xlo), xhi);
            float xcB = fminf(fmaxf(xnB, xlo), xhi);
            zfAn[lane] = xcA;
            zfBn[lane] = xcB;
            oxA[(size_t)(t + 1) * NXD + lane] = xcA;
            oxB[(size_t)(t + 1) * NXD + lane] = xcB;
            if (lane < 8)       zfAn[32 + lane] = uA;          // stage u_{t+1}
            else if (lane < 16) zfBn[32 + (lane - 8)] = uB;
        }
        __syncthreads();
    };

    // ---- main rollout: f steps t = 0 .. NT-2 ----
    for (int t = 0; t < NT - 2; t += 2) {
        step(t,     zfA0, zfB0, zfA1, zfB1, zhA0, zhB0, zhA1, zhB1,
                    hhA0, hhB0, hhA1, hhB1);
        step(t + 1, zfA1, zfB1, zfA0, zfB0, zhA1, zhB1, zhA0, zhB0,
                    hhA1, hhB1, hhA0, hhB0);
    }
    step(NT - 2, zfA0, zfB0, zfA1, zfB1, zhA0, zhB0, zhA1, zhB1,
                 hhA0, hhB0, hhA1, hhB1);          // t = 2046 (even)

    // ---- epilogue 1: y[NT-2] from hh0; h1 of final state (zh0) -> hh1 ----
    if (w == 2) {
        const int l = tt - 64;
        const int out = l & 15;
        const float* hhp = (l < 16) ? hhA0 : hhB0;
        const float* wr  = WH2T + out * 132;
        float acc = 0.f;
#pragma unroll
        for (int q = 0; q < NH / 4; q++) {
            float4 h4 = *(const float4*)(hhp + 4 * q);
            float4 w4 = *(const float4*)(wr + 4 * q);
            acc = __fmaf_rn(h4.x, w4.x, acc);
            acc = __fmaf_rn(h4.y, w4.y, acc);
            acc = __fmaf_rn(h4.z, w4.z, acc);
            acc = __fmaf_rn(h4.w, w4.w, acc);
        }
        float y = __fadd_rn(acc, bh2v);
        y = fminf(fmaxf(y, ylo), yhi);
        ((l < 16) ? oyA : oyB)[(size_t)(NT - 2) * NYD + out] = y;
    } else if (tt >= 128 && tt < 192) {
        const int j = tt - 128;
        float c0 = 0.f, c1 = 0.f, c2 = 0.f, c3 = 0.f;
#pragma unroll
        for (int q = 0; q < ZH_DIM / 4; q++) {
            float4 zA = *(const float4*)(zhA0 + 4 * q);
            float4 zB = *(const float4*)(zhB0 + 4 * q);
            c0 = __fmaf_rn(zA.x, wh[4 * q + 0], c0);
            c1 = __fmaf_rn(zA.x, wh[ZH_DIM + 4 * q + 0], c1);
            c2 = __fmaf_rn(zB.x, wh[4 * q + 0], c2);
            c3 = __fmaf_rn(zB.x, wh[ZH_DIM + 4 * q + 0], c3);
            c0 = __fmaf_rn(zA.y, wh[4 * q + 1], c0);
            c1 = __fmaf_rn(zA.y, wh[ZH_DIM + 4 * q + 1], c1);
            c2 = __fmaf_rn(zB.y, wh[4 * q + 1], c2);
            c3 = __fmaf_rn(zB.y, wh[ZH_DIM + 4 * q + 1], c3);
            c0 = __fmaf_rn(zA.z, wh[4 * q + 2], c0);
            c1 = __fmaf_rn(zA.z, wh[ZH_DIM + 4 * q + 2], c1);
            c2 = __fmaf_rn(zB.z, wh[4 * q + 2], c2);
            c3 = __fmaf_rn(zB.z, wh[ZH_DIM + 4 * q + 2], c3);
            c0 = __fmaf_rn(zA.w, wh[4 * q + 3], c0);
            c1 = __fmaf_rn(zA.w, wh[ZH_DIM + 4 * q + 3], c1);
            c2 = __fmaf_rn(zB.w, wh[4 * q + 3], c2);
            c3 = __fmaf_rn(zB.w, wh[ZH_DIM + 4 * q + 3], c3);
        }
        hhA1[j]      = xla_tanh(__fadd_rn(c0, bH0));
        hhA1[j + 64] = xla_tanh(__fadd_rn(c1, bH1));
        hhB1[j]      = xla_tanh(__fadd_rn(c2, bH0));
        hhB1[j + 64] = xla_tanh(__fadd_rn(c3, bH1));
    }
    __syncthreads();

    // ---- epilogue 2: y[NT-1] from hh1 ----
    if (w == 2) {
        const int l = tt - 64;
        const int out = l & 15;
        const float* hhp = (l < 16) ? hhA1 : hhB1;
        const float* wr  = WH2T + out * 132;
        float acc = 0.f;
#pragma unroll
        for (int q = 0; q < NH / 4; q++) {
            float4 h4 = *(const float4*)(hhp + 4 * q);
            float4 w4 = *(const float4*)(wr + 4 * q);
            acc = __fmaf_rn(h4.x, w4.x, acc);
            acc = __fmaf_rn(h4.y, w4.y, acc);
            acc = __fmaf_rn(h4.z, w4.z, acc);
            acc = __fmaf_rn(h4.w, w4.w, acc);
        }
        float y = __fadd_rn(acc, bh2v);
        y = fminf(fmaxf(y, ylo), yhi);
        ((l < 16) ? oyA : oyB)[(size_t)(NT - 1) * NYD + out] = y;
    }
}

extern "C" void kernel_launch(void* const* d_in, const int* in_sizes, int n_in,
                              void* d_out, int out_size) {
    (void)in_sizes; (void)n_in; (void)out_size;

    const float* x0   = (const float*)d_in[0];
    const float* u    = (const float*)d_in[1];
    const float* thf  = (const float*)d_in[2];
    const float* thh  = (const float*)d_in[3];
    const float* Wf1  = (const float*)d_in[4];
    const float* bf1  = (const float*)d_in[5];
    const float* Wf2  = (const float*)d_in[6];
    const float* bf2  = (const float*)d_in[7];
    const float* Wh1  = (const float*)d_in[8];
    const float* bh1  = (const float*)d_in[9];
    const float* Wh2  = (const float*)d_in[10];
    const float* bh2  = (const float*)d_in[11];
    const float* xmin = (const float*)d_in[12];
    const float* xmax = (const float*)d_in[13];
    const float* ymin = (const float*)d_in[14];
    const float* ymax = (const float*)d_in[15];

    float* outx = (float*)d_out;
    float* outy = outx + (size_t)NB * NT * NXD;

    ssm_kernel<<<NB / 2, THREADS>>>(
        x0, u, thf, thh, Wf1, bf1, Wf2, bf2, Wh1, bh1, Wh2, bh2,
        xmin, xmax, ymin, ymax, outx, outy);
}

// round 11
// speedup vs baseline: 1.7448x; 1.7448x over previous
#include <cuda_runtime.h>
#include <cstdint>
#include <cstddef>

// Problem constants
#define NB   512
#define NT   2048
#define NXD  32
#define NUD  8
#define NYD  16
#define NH   128
#define NTHD 4
#define ZF_DIM 44   // NXD + NUD + NTHD
#define ZH_DIM 36   // NXD + NTHD

#define THREADS 128   // 1 batch row per block, 4 warps

// Exact XLA EmitFastTanh — bitwise-matched to the reference (verified rel_err=0).
__device__ __forceinline__ float xla_tanh(float x) {
    const float kClamp = 7.90531110763549805f;
    float ax = fabsf(x);
    float xc = fminf(fmaxf(x, -kClamp), kClamp);
    float x2 = __fmul_rn(xc, xc);
    float p;
    p = __fmaf_rn(x2, -2.76076847742355e-16f, 2.00018790482477e-13f);
    p = __fmaf_rn(x2, p, -8.60467152213735e-11f);
    p = __fmaf_rn(x2, p,  5.12229709037114e-08f);
    p = __fmaf_rn(x2, p,  1.48572235717979e-05f);
    p = __fmaf_rn(x2, p,  6.37261928875436e-04f);
    p = __fmaf_rn(x2, p,  4.89352455891786e-03f);
    p = __fmul_rn(xc, p);
    float q;
    q = __fmaf_rn(x2, 1.19825839466702e-06f, 1.18534705686654e-04f);
    q = __fmaf_rn(x2, q, 2.26843463243900e-03f);
    q = __fmaf_rn(x2, q, 4.89352518554385e-03f);
    float r = __fdiv_rn(p, q);
    return (ax < 0.0004f) ? x : r;
}

// Named barriers by LOGICAL role pair (64 threads each).
#define BAR_F() asm volatile("bar.sync 1, 64;" ::: "memory")   // logical warps 0,1
#define BAR_H() asm volatile("bar.sync 2, 64;" ::: "memory")   // logical warps 2,3

__global__ void __launch_bounds__(THREADS, 4)
ssm_kernel(const float* __restrict__ x0g, const float* __restrict__ ug,
           const float* __restrict__ thfg, const float* __restrict__ thhg,
           const float* __restrict__ Wf1g, const float* __restrict__ bf1g,
           const float* __restrict__ Wf2g, const float* __restrict__ bf2g,
           const float* __restrict__ Wh1g, const float* __restrict__ bh1g,
           const float* __restrict__ Wh2g, const float* __restrict__ bh2g,
           const float* __restrict__ xming, const float* __restrict__ xmaxg,
           const float* __restrict__ yming, const float* __restrict__ ymaxg,
           float* __restrict__ outx, float* __restrict__ outy)
{
    __shared__ __align__(16) float WF2T[NXD * 132];   // WF2T[i*132+k] = Wf2[k][i]
    __shared__ __align__(16) float WH2T[NYD * 132];   // WH2T[i*132+k] = Wh2[k][i]
    __shared__ __align__(16) float hf[NH], hh[NH];
    __shared__ __align__(16) float zf0[48], zf1[48];  // [x(32)|u(8)|thf(4)|pad]
    __shared__ __align__(16) float zh0[48], zh1[48];  // [x_pre(32)|thh(4)|pad]
    __shared__ __align__(16) float bf2s[32];
    __shared__ __align__(16) float bh2s[16];
    __shared__ __align__(16) float consts[4];         // xlo xhi ylo yhi

    const int tt   = threadIdx.x;
    const int w    = tt >> 5;
    const int lane = tt & 31;
    const int b    = blockIdx.x;

    // Role rotation: co-resident blocks on an SM have bids spaced by 148=4*37,
    // so (bid>>2)&3 differs across all 4 of them -> each logical role lands on
    // a different SMSP per block, balancing issue load across sub-partitions.
    const int rot = (b >> 2) & 3;
    const int lw  = (w + 4 - rot) & 3;    // logical warp id (role)
    const int ltt = lw * 32 + lane;       // logical thread id 0..127

    const float* ub  = ug   + (size_t)b * NT * NUD;
    float*       oxb = outx + (size_t)b * NT * NXD;
    float*       oyb = outy + (size_t)b * NT * NYD;

    // ---- layer-1 weights into registers, per LOGICAL role ----
    // lw 0,1: f1 columns (ltt, ltt+64).  lw 2,3: h1 columns (j, j+64), j=ltt-64.
    float wA[ZF_DIM], wB[ZF_DIM];
    float bA, bB;
    if (lw < 2) {
#pragma unroll
        for (int k = 0; k < ZF_DIM; k++) {
            wA[k] = Wf1g[k * NH + ltt];
            wB[k] = Wf1g[k * NH + 64 + ltt];
        }
        bA = bf1g[ltt];
        bB = bf1g[64 + ltt];
    } else {
        const int j = ltt - 64;
#pragma unroll
        for (int k = 0; k < ZH_DIM; k++) {
            wA[k] = Wh1g[k * NH + j];
            wB[k] = Wh1g[k * NH + 64 + j];
        }
        bA = bh1g[j];
        bB = bh1g[ltt];   // j + 64 == ltt
    }

    // ---- smem staging (role-independent, physical tt) ----
    for (int e = tt; e < NH * NXD; e += THREADS) {
        int k = e >> 5, i = e & 31;
        WF2T[i * 132 + k] = Wf2g[e];
    }
    for (int e = tt; e < NH * NYD; e += THREADS) {
        int k = e >> 4, i = e & 15;
        WH2T[i * 132 + k] = Wh2g[e];
    }
    if (tt < 32) bf2s[tt] = bf2g[tt];
    if (tt < 16) bh2s[tt] = bh2g[tt];
    if (tt == 0) {
        consts[0] = xming[0]; consts[1] = xmaxg[0];
        consts[2] = yming[0]; consts[3] = ymaxg[0];
    }
    if (tt < 32) {
        float xv = x0g[b * 32 + tt];
        zf0[tt] = xv;
        zh1[tt] = xv;          // h at t=0 reads zh1 (y0 = h(x_0))
        oxb[tt] = xv;          // x output index 0 is x_0
    }
    if (tt >= 32 && tt < 40) zf0[tt] = ub[tt - 32];                // u_0
    if (tt >= 40 && tt < 44) {
        float th = thfg[b * 4 + (tt - 40)];
        zf0[tt] = th; zf1[tt] = th;                                // theta_f both bufs
    }
    if (tt < 4) {
        float th = thhg[b * 4 + tt];
        zh0[32 + tt] = th; zh1[32 + tt] = th;                      // theta_h both bufs
    }
    __syncthreads();

    const float bf2v = bf2s[lane];
    const float bh2v = bh2s[lane & 15];

    // ---- one step, buffer parity statically resolved ----
    // zfc: f input; zfn: clamped carry out (+u stage); zhw: pre-clamp x out
    // (h input for NEXT iteration); zhr: h input for THIS iteration.
    auto step = [&](int t, const float* zfc, float* zfn, float* zhw, const float* zhr) {
        if (lw < 2) {
            // ---- f1: units ltt, ltt+64; strict ascending-k 44-chains ----
            float a0 = 0.f, a1 = 0.f;
#pragma unroll
            for (int q = 0; q < ZF_DIM / 4; q++) {
                float4 z4 = *(const float4*)(zfc + 4 * q);
                a0 = __fmaf_rn(z4.x, wA[4 * q + 0], a0);
                a1 = __fmaf_rn(z4.x, wB[4 * q + 0], a1);
                a0 = __fmaf_rn(z4.y, wA[4 * q + 1], a0);
                a1 = __fmaf_rn(z4.y, wB[4 * q + 1], a1);
                a0 = __fmaf_rn(z4.z, wA[4 * q + 2], a0);
                a1 = __fmaf_rn(z4.z, wB[4 * q + 2], a1);
                a0 = __fmaf_rn(z4.w, wA[4 * q + 3], a0);
                a1 = __fmaf_rn(z4.w, wB[4 * q + 3], a1);
            }
            hf[ltt]      = xla_tanh(__fadd_rn(a0, bA));
            hf[ltt + 64] = xla_tanh(__fadd_rn(a1, bB));
            BAR_F();
            if (lw == 0) {
                // ---- f2: strict 128-chain, smem weights (conflict-free .128) ----
                float acc = 0.f;
                const float* wr = WF2T + lane * 132;
#pragma unroll
                for (int q = 0; q < NH / 4; q++) {
                    float4 h4 = *(const float4*)(hf + 4 * q);
                    float4 w4 = *(const float4*)(wr + 4 * q);
                    acc = __fmaf_rn(h4.x, w4.x, acc);
                    acc = __fmaf_rn(h4.y, w4.y, acc);
                    acc = __fmaf_rn(h4.z, w4.z, acc);
                    acc = __fmaf_rn(h4.w, w4.w, acc);
                }
                float dx = __fadd_rn(acc, bf2v);
                float xn = __fadd_rn(zfc[lane], dx);     // pre-clamp x_new
                zhw[lane] = xn;                          // h input for next iteration
                float xc = fminf(fmaxf(xn, consts[0]), consts[1]);
                zfn[lane] = xc;                          // clamped carry
                oxb[(size_t)(t + 1) * NXD + lane] = xc;
            }
        } else {
            // ---- h-side ----
            float ureg = 0.f;
            if (lw == 3) {
                if (lane < 8) ureg = ub[(size_t)(t + 1) * NUD + lane];
                if (lane == 0 && t + 8 < NT)
                    asm volatile("prefetch.global.L2 [%0];" :: "l"(ub + (size_t)(t + 8) * NUD));
            }
            const int j = ltt - 64;
            float b0 = 0.f, b1 = 0.f;
#pragma unroll
            for (int q = 0; q < ZH_DIM / 4; q++) {
                float4 z4 = *(const float4*)(zhr + 4 * q);
                b0 = __fmaf_rn(z4.x, wA[4 * q + 0], b0);
                b1 = __fmaf_rn(z4.x, wB[4 * q + 0], b1);
                b0 = __fmaf_rn(z4.y, wA[4 * q + 1], b0);
                b1 = __fmaf_rn(z4.y, wB[4 * q + 1], b1);
                b0 = __fmaf_rn(z4.z, wA[4 * q + 2], b0);
                b1 = __fmaf_rn(z4.z, wB[4 * q + 2], b1);
                b0 = __fmaf_rn(z4.w, wA[4 * q + 3], b0);
                b1 = __fmaf_rn(z4.w, wB[4 * q + 3], b1);
            }
            hh[j]      = xla_tanh(__fadd_rn(b0, bA));
            hh[j + 64] = xla_tanh(__fadd_rn(b1, bB));
            BAR_H();
            if (lw == 2 && lane < 16) {
                // ---- h2: strict 128-chain from smem ----
                float acc = 0.f;
                const float* wr = WH2T + lane * 132;
#pragma unroll
                for (int q = 0; q < NH / 4; q++) {
                    float4 h4 = *(const float4*)(hh + 4 * q);
                    float4 w4 = *(const float4*)(wr + 4 * q);
                    acc = __fmaf_rn(h4.x, w4.x, acc);
                    acc = __fmaf_rn(h4.y, w4.y, acc);
                    acc = __fmaf_rn(h4.z, w4.z, acc);
                    acc = __fmaf_rn(h4.w, w4.w, acc);
                }
                float y = __fadd_rn(acc, bh2v);
                if (t > 0) y = fminf(fmaxf(y, consts[2]), consts[3]);  // y0 unclamped
                oyb[(size_t)t * NYD + lane] = y;
            }
            if (lw == 3 && lane < 8)
                zfn[32 + lane] = ureg;                   // stage u_{t+1}
        }
        __syncthreads();
    };

    // ---- main rollout: iterations t = 0 .. NT-2 (even/odd specialized) ----
    for (int t = 0; t < NT - 2; t += 2) {
        step(t,     zf0, zf1, zh0, zh1);
        step(t + 1, zf1, zf0, zh1, zh0);
    }
    step(NT - 2, zf0, zf1, zh0, zh1);   // t = 2046 (even)

    // ---- epilogue: h for the final state (written to zh0) -> y index NT-1 ----
    if (lw >= 2) {
        const int j = ltt - 64;
        float b0 = 0.f, b1 = 0.f;
#pragma unroll
        for (int q = 0; q < ZH_DIM / 4; q++) {
            float4 z4 = *(const float4*)(zh0 + 4 * q);
            b0 = __fmaf_rn(z4.x, wA[4 * q + 0], b0);
            b1 = __fmaf_rn(z4.x, wB[4 * q + 0], b1);
            b0 = __fmaf_rn(z4.y, wA[4 * q + 1], b0);
            b1 = __fmaf_rn(z4.y, wB[4 * q + 1], b1);
            b0 = __fmaf_rn(z4.z, wA[4 * q + 2], b0);
            b1 = __fmaf_rn(z4.z, wB[4 * q + 2], b1);
            b0 = __fmaf_rn(z4.w, wA[4 * q + 3], b0);
            b1 = __fmaf_rn(z4.w, wB[4 * q + 3], b1);
        }
        hh[j]      = xla_tanh(__fadd_rn(b0, bA));
        hh[j + 64] = xla_tanh(__fadd_rn(b1, bB));
        BAR_H();
        if (lw == 2 && lane < 16) {
            float acc = 0.f;
            const float* wr = WH2T + lane * 132;
#pragma unroll
            for (int q = 0; q < NH / 4; q++) {
                float4 h4 = *(const float4*)(hh + 4 * q);
                float4 w4 = *(const float4*)(wr + 4 * q);
                acc = __fmaf_rn(h4.x, w4.x, acc);
                acc = __fmaf_rn(h4.y, w4.y, acc);
                acc = __fmaf_rn(h4.z, w4.z, acc);
                acc = __fmaf_rn(h4.w, w4.w, acc);
            }
            float y = __fadd_rn(acc, bh2v);
            y = fminf(fmaxf(y, consts[2]), consts[3]);
            oyb[(size_t)(NT - 1) * NYD + lane] = y;
        }
    }
}

extern "C" void kernel_launch(void* const* d_in, const int* in_sizes, int n_in,
                              void* d_out, int out_size) {
    (void)in_sizes; (void)n_in; (void)out_size;

    const float* x0   = (const float*)d_in[0];
    const float* u    = (const float*)d_in[1];
    const float* thf  = (const float*)d_in[2];
    const float* thh  = (const float*)d_in[3];
    const float* Wf1  = (const float*)d_in[4];
    const float* bf1  = (const float*)d_in[5];
    const float* Wf2  = (const float*)d_in[6];
    const float* bf2  = (const float*)d_in[7];
    const float* Wh1  = (const float*)d_in[8];
    const float* bh1  = (const float*)d_in[9];
    const float* Wh2  = (const float*)d_in[10];
    const float* bh2  = (const float*)d_in[11];
    const float* xmin = (const float*)d_in[12];
    const float* xmax = (const float*)d_in[13];
    const float* ymin = (const float*)d_in[14];
    const float* ymax = (const float*)d_in[15];

    float* outx = (float*)d_out;
    float* outy = outx + (size_t)NB * NT * NXD;

    ssm_kernel<<<NB, THREADS>>>(
        x0, u, thf, thh, Wf1, bf1, Wf2, bf2, Wh1, bh1, Wh2, bh2,
        xmin, xmax, ymin, ymax, outx, outy);
}

// round 12
// speedup vs baseline: 2.0057x; 1.1495x over previous
#include <cuda_runtime.h>
#include <cstdint>
#include <cstddef>

// Problem constants
#define NB   512
#define NT   2048
#define NXD  32
#define NUD  8
#define NYD  16
#define NH   128
#define ZF_DIM 44   // NXD + NUD + NTHD
#define ZH_DIM 36   // NXD + NTHD

// Scratch: h-inputs for every y output. [b][t][32]; t=0 holds x_0, t>=1 holds
// pre-clamp x_new produced by rollout step t-1. Static device array (sanctioned).
__device__ float g_xpre[(size_t)NB * NT * NXD];

// Exact XLA EmitFastTanh — bitwise-matched to the reference (verified rel_err=0).
__device__ __forceinline__ float xla_tanh(float x) {
    const float kClamp = 7.90531110763549805f;
    float ax = fabsf(x);
    float xc = fminf(fmaxf(x, -kClamp), kClamp);
    float x2 = __fmul_rn(xc, xc);
    float p;
    p = __fmaf_rn(x2, -2.76076847742355e-16f, 2.00018790482477e-13f);
    p = __fmaf_rn(x2, p, -8.60467152213735e-11f);
    p = __fmaf_rn(x2, p,  5.12229709037114e-08f);
    p = __fmaf_rn(x2, p,  1.48572235717979e-05f);
    p = __fmaf_rn(x2, p,  6.37261928875436e-04f);
    p = __fmaf_rn(x2, p,  4.89352455891786e-03f);
    p = __fmul_rn(xc, p);
    float q;
    q = __fmaf_rn(x2, 1.19825839466702e-06f, 1.18534705686654e-04f);
    q = __fmaf_rn(x2, q, 2.26843463243900e-03f);
    q = __fmaf_rn(x2, q, 4.89352518554385e-03f);
    float r = __fdiv_rn(p, q);
    return (ax < 0.0004f) ? x : r;
}

// f2 segment weights live in the SAME register arrays as f1 weights (role
// union — avoids live-range double counting). k is always a compile-time
// constant here so the ternary folds to a direct register reference.
#define WS(k) ((k) < 44 ? wA[(k)] : wB[(k) - 44])

#define BAR_SEG() asm volatile("bar.sync 1, 64;" ::: "memory")  // lw0 + lw1

// ===================== Kernel 1: serial f-rollout =====================
__global__ void __launch_bounds__(128, 4)
f_rollout(const float* __restrict__ x0g, const float* __restrict__ ug,
          const float* __restrict__ thfg,
          const float* __restrict__ Wf1g, const float* __restrict__ bf1g,
          const float* __restrict__ Wf2g, const float* __restrict__ bf2g,
          const float* __restrict__ xming, const float* __restrict__ xmaxg,
          float* __restrict__ outx)
{
    __shared__ __align__(16) float hf[NH];
    __shared__ __align__(16) float partial[32];
    __shared__ __align__(16) float zf0[48], zf1[48];  // [x(32)|u(8)|thf(4)|pad]

    const int tt   = threadIdx.x;
    const int w    = tt >> 5;
    const int lane = tt & 31;
    const int b    = blockIdx.x;

    // SMSP role rotation (proven win in r11).
    const int rot = (b >> 2) & 3;
    const int lw  = (w + 4 - rot) & 3;

    const float* ub  = ug   + (size_t)b * NT * NUD;
    float*       oxb = outx + (size_t)b * NT * NXD;
    float*       xpb = g_xpre + (size_t)b * NT * NXD;

    // ---- register weights by role ----
    // lw2: f1 units (lane, lane+64).  lw3: f1 units (32+lane, 96+lane).
    // lw0: f2 seg A (k=0..63).        lw1: f2 seg B (k=64..127).
    float wA[44], wB[44];
    float bA = 0.f, bB = 0.f, bf2v = 0.f, xlo = 0.f, xhi = 0.f;
    int u0 = 0;
    if (lw >= 2) {
        u0 = (lw == 2) ? lane : 32 + lane;
#pragma unroll
        for (int k = 0; k < ZF_DIM; k++) {
            wA[k] = Wf1g[k * NH + u0];
            wB[k] = Wf1g[k * NH + u0 + 64];
        }
        bA = bf1g[u0];
        bB = bf1g[u0 + 64];
    } else if (lw == 0) {
#pragma unroll
        for (int k = 0; k < 64; k++) WS(k) = Wf2g[k * NXD + lane];
    } else {
#pragma unroll
        for (int k = 0; k < 64; k++) WS(k) = Wf2g[(64 + k) * NXD + lane];
        bf2v = bf2g[lane];
        xlo = xming[0]; xhi = xmaxg[0];
    }

    // ---- state init ----
    if (tt < 32) {
        float xv = x0g[b * 32 + tt];
        zf0[tt] = xv;
        oxb[tt] = xv;            // x output index 0 is x_0
        xpb[tt] = xv;            // h input for y[0] is x_0
    }
    if (tt >= 32 && tt < 40) zf0[tt] = ub[tt - 32];            // u_0
    if (tt >= 40 && tt < 44) {
        float th = thfg[b * 4 + (tt - 40)];
        zf0[tt] = th; zf1[tt] = th;                            // theta_f both bufs
    }
    __syncthreads();

    // ---- one step, parity statically resolved ----
    auto step = [&](int t, const float* zfc, float* zfn) {
        float ureg = 0.f;
        if (lw >= 2) {
            // f1: two strict ascending-k 44-chains (reg weights, broadcast z)
            float a0 = 0.f, a1 = 0.f;
#pragma unroll
            for (int q = 0; q < ZF_DIM / 4; q++) {
                float4 z4 = *(const float4*)(zfc + 4 * q);
                a0 = __fmaf_rn(z4.x, wA[4 * q + 0], a0);
                a1 = __fmaf_rn(z4.x, wB[4 * q + 0], a1);
                a0 = __fmaf_rn(z4.y, wA[4 * q + 1], a0);
                a1 = __fmaf_rn(z4.y, wB[4 * q + 1], a1);
                a0 = __fmaf_rn(z4.z, wA[4 * q + 2], a0);
                a1 = __fmaf_rn(z4.z, wB[4 * q + 2], a1);
                a0 = __fmaf_rn(z4.w, wA[4 * q + 3], a0);
                a1 = __fmaf_rn(z4.w, wB[4 * q + 3], a1);
            }
            hf[u0]      = xla_tanh(__fadd_rn(a0, bA));
            hf[u0 + 64] = xla_tanh(__fadd_rn(a1, bB));
        } else if (lw == 0) {
            if (lane < 8) ureg = ub[(size_t)(t + 1) * NUD + lane];
            if (lane == 8 && t + 8 < NT)
                asm volatile("prefetch.global.L2 [%0];" :: "l"(ub + (size_t)(t + 8) * NUD));
        }
        __syncthreads();                       // hf ready

        if (lw == 0) {
            // f2 segment A: ordered k = 0..63, reg weights, broadcast hf
            float acc = 0.f;
#pragma unroll
            for (int q = 0; q < 16; q++) {
                float4 h4 = *(const float4*)(hf + 4 * q);
                acc = __fmaf_rn(h4.x, WS(4 * q + 0), acc);
                acc = __fmaf_rn(h4.y, WS(4 * q + 1), acc);
                acc = __fmaf_rn(h4.z, WS(4 * q + 2), acc);
                acc = __fmaf_rn(h4.w, WS(4 * q + 3), acc);
            }
            partial[lane] = acc;
            BAR_SEG();
            if (lane < 8) zfn[32 + lane] = ureg;     // stage u_{t+1}
        } else if (lw == 1) {
            BAR_SEG();
            // f2 segment B: continue the SAME accumulator, k = 64..127
            float acc = partial[lane];
#pragma unroll
            for (int q = 0; q < 16; q++) {
                float4 h4 = *(const float4*)(hf + 64 + 4 * q);
                acc = __fmaf_rn(h4.x, WS(4 * q + 0), acc);
                acc = __fmaf_rn(h4.y, WS(4 * q + 1), acc);
                acc = __fmaf_rn(h4.z, WS(4 * q + 2), acc);
                acc = __fmaf_rn(h4.w, WS(4 * q + 3), acc);
            }
            float dx = __fadd_rn(acc, bf2v);
            float xn = __fadd_rn(zfc[lane], dx);     // pre-clamp x_new
            xpb[(size_t)(t + 1) * NXD + lane] = xn;  // h input for y[t+1]
            float xc = fminf(fmaxf(xn, xlo), xhi);
            zfn[lane] = xc;                          // clamped carry
            oxb[(size_t)(t + 1) * NXD + lane] = xc;
        }
        __syncthreads();
    };

    for (int t = 0; t < NT - 2; t += 2) {
        step(t,     zf0, zf1);
        step(t + 1, zf1, zf0);
    }
    step(NT - 2, zf0, zf1);    // t = 2046 (even)
}

// ===================== Kernel 2: batch h evaluation =====================
// y[b][t] = h(g_xpre[b][t]); clamp for t>0; y[b][0] unclamped.
// 4096 blocks = 512 b x 8 stripes of 256 t; tiles of 4 rows.
__global__ void __launch_bounds__(128, 5)
h_eval(const float* __restrict__ thhg,
       const float* __restrict__ Wh1g, const float* __restrict__ bh1g,
       const float* __restrict__ Wh2g, const float* __restrict__ bh2g,
       const float* __restrict__ yming, const float* __restrict__ ymaxg,
       float* __restrict__ outy)
{
    __shared__ __align__(16) float WH2T[NYD * 132];   // WH2T[i*132+k] = Wh2[k][i]
    __shared__ __align__(16) float zsm[4 * 40];       // 4 rows x [x(32)|thh(4)|pad]
    __shared__ __align__(16) float hhs[4 * NH];
    __shared__ __align__(16) float bh2s[16];

    const int tt = threadIdx.x;
    const int b      = blockIdx.x >> 3;
    const int stripe = blockIdx.x & 7;
    const int t0base = stripe * (NT / 8);   // 256 t's per stripe

    // h1 weights: one unit per thread, registers
    float wh1[ZH_DIM];
#pragma unroll
    for (int k = 0; k < ZH_DIM; k++) wh1[k] = Wh1g[k * NH + tt];
    const float bh1v = bh1g[tt];
    const float ylo = yming[0], yhi = ymaxg[0];

    for (int e = tt; e < NYD * 132; e += 128) {
        int i = e / 132, k = e - i * 132;
        if (k < NH) WH2T[e] = Wh2g[k * NYD + i];
    }
    if (tt < 16) bh2s[tt] = bh2g[tt];
    if (tt < 16) {                       // theta_h + zero pad, persistent slots
        int r = tt >> 2, j = tt & 3;
        zsm[r * 40 + 32 + j] = thhg[b * 4 + j];
        zsm[r * 40 + 36 + j] = 0.f;
    }
    __syncthreads();

    const float* xp  = g_xpre + (size_t)b * NT * NXD;
    float*       oyb = outy   + (size_t)b * NT * NYD;

    for (int tile = 0; tile < 64; tile++) {
        const int t0 = t0base + tile * 4;
        // load 4 rows of x (contiguous 512B, fully coalesced)
        {
            int r = tt >> 5, k = tt & 31;
            zsm[r * 40 + k] = xp[(size_t)(t0 + r) * NXD + k];
        }
        __syncthreads();

        // phase 1: h1 unit tt for 4 rows (4 independent ascending 36-chains)
        float a0 = 0.f, a1 = 0.f, a2 = 0.f, a3 = 0.f;
#pragma unroll
        for (int q = 0; q < ZH_DIM / 4; q++) {
            float4 z0 = *(const float4*)(zsm + 0 * 40 + 4 * q);
            float4 z1 = *(const float4*)(zsm + 1 * 40 + 4 * q);
            float4 z2 = *(const float4*)(zsm + 2 * 40 + 4 * q);
            float4 z3 = *(const float4*)(zsm + 3 * 40 + 4 * q);
            a0 = __fmaf_rn(z0.x, wh1[4 * q + 0], a0);
            a1 = __fmaf_rn(z1.x, wh1[4 * q + 0], a1);
            a2 = __fmaf_rn(z2.x, wh1[4 * q + 0], a2);
            a3 = __fmaf_rn(z3.x, wh1[4 * q + 0], a3);
            a0 = __fmaf_rn(z0.y, wh1[4 * q + 1], a0);
            a1 = __fmaf_rn(z1.y, wh1[4 * q + 1], a1);
            a2 = __fmaf_rn(z2.y, wh1[4 * q + 1], a2);
            a3 = __fmaf_rn(z3.y, wh1[4 * q + 1], a3);
            a0 = __fmaf_rn(z0.z, wh1[4 * q + 2], a0);
            a1 = __fmaf_rn(z1.z, wh1[4 * q + 2], a1);
            a2 = __fmaf_rn(z2.z, wh1[4 * q + 2], a2);
            a3 = __fmaf_rn(z3.z, wh1[4 * q + 2], a3);
            a0 = __fmaf_rn(z0.w, wh1[4 * q + 3], a0);
            a1 = __fmaf_rn(z1.w, wh1[4 * q + 3], a1);
            a2 = __fmaf_rn(z2.w, wh1[4 * q + 3], a2);
            a3 = __fmaf_rn(z3.w, wh1[4 * q + 3], a3);
        }
        hhs[0 * NH + tt] = xla_tanh(__fadd_rn(a0, bh1v));
        hhs[1 * NH + tt] = xla_tanh(__fadd_rn(a1, bh1v));
        hhs[2 * NH + tt] = xla_tanh(__fadd_rn(a2, bh1v));
        hhs[3 * NH + tt] = xla_tanh(__fadd_rn(a3, bh1v));
        __syncthreads();

        // phase 2: (row, output) per thread; strict ascending 128-chain
        if (tt < 64) {
            const int r = tt >> 4, i = tt & 15;
            const float* hh = hhs + r * NH;
            const float* wr = WH2T + i * 132;
            float acc = 0.f;
#pragma unroll
            for (int q = 0; q < NH / 4; q++) {
                float4 h4 = *(const float4*)(hh + 4 * q);
                float4 w4 = *(const float4*)(wr + 4 * q);
                acc = __fmaf_rn(h4.x, w4.x, acc);
                acc = __fmaf_rn(h4.y, w4.y, acc);
                acc = __fmaf_rn(h4.z, w4.z, acc);
                acc = __fmaf_rn(h4.w, w4.w, acc);
            }
            float y = __fadd_rn(acc, bh2s[i]);
            const int gt = t0 + r;
            if (gt > 0) y = fminf(fmaxf(y, ylo), yhi);   // y[0] unclamped
            oyb[(size_t)gt * NYD + i] = y;
        }
        __syncthreads();
    }
}

extern "C" void kernel_launch(void* const* d_in, const int* in_sizes, int n_in,
                              void* d_out, int out_size) {
    (void)in_sizes; (void)n_in; (void)out_size;

    const float* x0   = (const float*)d_in[0];
    const float* u    = (const float*)d_in[1];
    const float* thf  = (const float*)d_in[2];
    const float* thh  = (const float*)d_in[3];
    const float* Wf1  = (const float*)d_in[4];
    const float* bf1  = (const float*)d_in[5];
    const float* Wf2  = (const float*)d_in[6];
    const float* bf2  = (const float*)d_in[7];
    const float* Wh1  = (const float*)d_in[8];
    const float* bh1  = (const float*)d_in[9];
    const float* Wh2  = (const float*)d_in[10];
    const float* bh2  = (const float*)d_in[11];
    const float* xmin = (const float*)d_in[12];
    const float* xmax = (const float*)d_in[13];
    const float* ymin = (const float*)d_in[14];
    const float* ymax = (const float*)d_in[15];

    float* outx = (float*)d_out;
    float* outy = outx + (size_t)NB * NT * NXD;

    f_rollout<<<NB, 128>>>(x0, u, thf, Wf1, bf1, Wf2, bf2, xmin, xmax, outx);
    h_eval<<<NB * 8, 128>>>(thh, Wh1, bh1, Wh2, bh2, ymin, ymax, outy);
}